// round 3
// baseline (speedup 1.0000x reference)
#include <cuda_runtime.h>
#include <cstdint>

// ---------------------------------------------------------------------------
// LCN_4698694222614: 3-layer locally-connected net + FC
//   B=512, IN=16384, DIMS={8192,4096,2048}, K=32, OUT=16
// Strategy:
//   1) transpose x -> xT (feature-major) so gathers are coalesced rows
//   2) per-layer: one block per output unit; 128 thr x float4 covers B=512
//   3) FC: j-tiled partial sums + atomicAdd onto bias-initialized out
// knn indices arrive as int32 (JAX x64 disabled downcasts int64->int32);
// a device-side probe handles the int64 case anyway.
// ---------------------------------------------------------------------------

#define BATCH 512
#define B4    128          // BATCH / 4 (float4 lanes)
#define KNN   32

// scratch (device globals: allocation-free rule)
__device__ float g_xT[16384 * BATCH];   // 32 MB
__device__ float g_y0[ 8192 * BATCH];   // 16 MB
__device__ float g_y1[ 4096 * BATCH];   //  8 MB
__device__ float g_y2[ 2048 * BATCH];   //  4 MB
__device__ int   g_knn_stride;          // 1 = int32, 2 = int64 (low word)

// ---- probe knn dtype: int64 little-endian => odd 32-bit words all zero ----
__global__ void detect_kernel(const int* __restrict__ knn0)
{
    if (threadIdx.x == 0) {
        int stride = 2;
        for (int i = 1; i < 128; i += 2)
            if (knn0[i] != 0) { stride = 1; break; }
        g_knn_stride = stride;
    }
}

// ---- transpose x (512, C) -> xT (C, 512) ----------------------------------
__global__ void transpose_kernel(const float* __restrict__ x, int C)
{
    __shared__ float tile[32][33];
    int c0 = blockIdx.x * 32;
    int b0 = blockIdx.y * 32;
    int tx = threadIdx.x;           // 0..31
    int ty = threadIdx.y;           // 0..7
#pragma unroll
    for (int i = 0; i < 32; i += 8)
        tile[ty + i][tx] = x[(size_t)(b0 + ty + i) * C + (c0 + tx)];
    __syncthreads();
#pragma unroll
    for (int i = 0; i < 32; i += 8)
        g_xT[(size_t)(c0 + ty + i) * BATCH + (b0 + tx)] = tile[tx][ty + i];
}

// ---- one LCN layer: yT[j, :] = relu(sum_k xT[knn[j,k], :] * w[j,k] + b[j]) -
__global__ void __launch_bounds__(B4)
layer_kernel(const float* __restrict__ srcT,
             const int* __restrict__ knn,
             const float* __restrict__ w,
             const float* __restrict__ bias,
             float* __restrict__ dstT)
{
    const int j   = blockIdx.x;
    const int tid = threadIdx.x;            // 0..127

    __shared__ int   sidx[KNN];
    __shared__ float sw[KNN];
    if (tid < KNN) {
        const int stride = g_knn_stride;    // 1 (int32) or 2 (int64 low word)
        sidx[tid] = knn[((size_t)j * KNN + tid) * stride];
        sw[tid]   = w[(size_t)j * KNN + tid];
    }
    __syncthreads();

    const float4* src4 = (const float4*)srcT;
    float4 acc = make_float4(0.f, 0.f, 0.f, 0.f);

#pragma unroll
    for (int k = 0; k < KNN; ++k) {
        const float4 v = __ldg(&src4[(size_t)sidx[k] * B4 + tid]);
        const float wk = sw[k];
        acc.x = fmaf(v.x, wk, acc.x);
        acc.y = fmaf(v.y, wk, acc.y);
        acc.z = fmaf(v.z, wk, acc.z);
        acc.w = fmaf(v.w, wk, acc.w);
    }

    const float bb = bias[j];
    acc.x = fmaxf(acc.x + bb, 0.f);
    acc.y = fmaxf(acc.y + bb, 0.f);
    acc.z = fmaxf(acc.z + bb, 0.f);
    acc.w = fmaxf(acc.w + bb, 0.f);

    ((float4*)dstT)[(size_t)j * B4 + tid] = acc;
}

// ---- FC: out[b, o] = fc_b[o] + sum_j y2T[j, b] * fc_w[j, o] ---------------
__global__ void fc_init_kernel(float* __restrict__ out, const float* __restrict__ fc_b)
{
    int i = blockIdx.x * blockDim.x + threadIdx.x;
    if (i < BATCH * 16) out[i] = fc_b[i & 15];
}

__global__ void __launch_bounds__(128)
fc_kernel(const float* __restrict__ fc_w, float* __restrict__ out)
{
    // grid.x: 4 batch tiles of 128; grid.y: 16 j tiles of 128 (2048 total)
    const int b  = blockIdx.x * 128 + threadIdx.x;
    const int j0 = blockIdx.y * 128;

    float acc[16];
#pragma unroll
    for (int o = 0; o < 16; ++o) acc[o] = 0.f;

    for (int jj = 0; jj < 128; ++jj) {
        const int   j = j0 + jj;
        const float v = g_y2[(size_t)j * BATCH + b];
#pragma unroll
        for (int o = 0; o < 16; ++o)
            acc[o] = fmaf(v, __ldg(&fc_w[j * 16 + o]), acc[o]);
    }
#pragma unroll
    for (int o = 0; o < 16; ++o)
        atomicAdd(&out[b * 16 + o], acc[o]);
}

// ---------------------------------------------------------------------------
extern "C" void kernel_launch(void* const* d_in, const int* in_sizes, int n_in,
                              void* d_out, int out_size)
{
    const float *x, *w0, *b0, *w1, *b1, *w2, *b2, *fcw, *fcb;
    const int *k0, *k1, *k2;

    // Disambiguate metadata ordering via element counts:
    //   dict order:      x,w0,b0,knn0,w1,b1,knn1,w2,b2,knn2,fc_w,fc_b
    //   signature order: x,w0,b0,w1,b1,w2,b2,fc_w,fc_b,knn0,knn1,knn2
    // in_sizes[3] = 262144 (knn0) in dict order, 131072 (w1) in signature order.
    if (in_sizes[3] == 262144) {
        x   = (const float*)d_in[0];
        w0  = (const float*)d_in[1];  b0 = (const float*)d_in[2];
        k0  = (const int*)d_in[3];
        w1  = (const float*)d_in[4];  b1 = (const float*)d_in[5];
        k1  = (const int*)d_in[6];
        w2  = (const float*)d_in[7];  b2 = (const float*)d_in[8];
        k2  = (const int*)d_in[9];
        fcw = (const float*)d_in[10]; fcb = (const float*)d_in[11];
    } else {
        x   = (const float*)d_in[0];
        w0  = (const float*)d_in[1];  b0 = (const float*)d_in[2];
        w1  = (const float*)d_in[3];  b1 = (const float*)d_in[4];
        w2  = (const float*)d_in[5];  b2 = (const float*)d_in[6];
        fcw = (const float*)d_in[7];  fcb = (const float*)d_in[8];
        k0  = (const int*)d_in[9];
        k1  = (const int*)d_in[10];
        k2  = (const int*)d_in[11];
    }

    float *p_xT, *p_y0, *p_y1, *p_y2;
    cudaGetSymbolAddress((void**)&p_xT, g_xT);
    cudaGetSymbolAddress((void**)&p_y0, g_y0);
    cudaGetSymbolAddress((void**)&p_y1, g_y1);
    cudaGetSymbolAddress((void**)&p_y2, g_y2);

    float* out = (float*)d_out;

    // 0) probe knn dtype (int32 vs int64)
    detect_kernel<<<1, 32>>>(k0);

    // 1) transpose x (512, 16384) -> xT (16384, 512)
    transpose_kernel<<<dim3(16384 / 32, BATCH / 32), dim3(32, 8)>>>(x, 16384);

    // 2) three LCN layers (feature-major in/out)
    layer_kernel<<<8192, B4>>>(p_xT, k0, w0, b0, p_y0);
    layer_kernel<<<4096, B4>>>(p_y0, k1, w1, b1, p_y1);
    layer_kernel<<<2048, B4>>>(p_y1, k2, w2, b2, p_y2);

    // 3) FC head
    fc_init_kernel<<<(BATCH * 16 + 255) / 256, 256>>>(out, fcb);
    fc_kernel<<<dim3(BATCH / 128, 2048 / 128), 128>>>(fcw, out);
}

// round 4
// speedup vs baseline: 1.3219x; 1.3219x over previous
#include <cuda_runtime.h>
#include <cuda_fp16.h>
#include <cstdint>

// ---------------------------------------------------------------------------
// LCN_4698694222614: 3-layer locally-connected net + FC
//   B=512, IN=16384, DIMS={8192,4096,2048}, K=32, OUT=16
// The gather layers are bound by the ~6300 B/cyc LTS (L2) chip cap, so the
// only lever is bytes: activations are stored as fp16 (halves L2 traffic),
// weights + accumulation stay fp32.  Layout is feature-major so every gather
// is a coalesced row read.
// ---------------------------------------------------------------------------

#define BATCH 512
#define KNN   32

// scratch (device globals: allocation-free rule)  — fp16 activations
__device__ __half g_xT[16384 * BATCH];   // 16 MB
__device__ __half g_y0[ 8192 * BATCH];   //  8 MB
__device__ __half g_y1[ 4096 * BATCH];   //  4 MB
__device__ __half g_y2[ 2048 * BATCH];   //  2 MB
__device__ int    g_knn_stride;          // 1 = int32, 2 = int64 (low word)

// ---- probe knn dtype (parallel): int64 LE => odd 32-bit words all zero ----
__global__ void detect_kernel(const int* __restrict__ knn0)
{
    // 32 threads sample odd words 1,3,...,63; any nonzero => int32
    int v = knn0[2 * threadIdx.x + 1];
    unsigned any = __ballot_sync(0xFFFFFFFFu, v != 0);
    if (threadIdx.x == 0) g_knn_stride = any ? 1 : 2;
}

// ---- transpose x (512, C) fp32 -> xT (C, 512) fp16 ------------------------
__global__ void transpose_kernel(const float* __restrict__ x, int C)
{
    __shared__ float tile[32][33];
    int c0 = blockIdx.x * 32;
    int b0 = blockIdx.y * 32;
    int tx = threadIdx.x;           // 0..31
    int ty = threadIdx.y;           // 0..7
#pragma unroll
    for (int i = 0; i < 32; i += 8)
        tile[ty + i][tx] = x[(size_t)(b0 + ty + i) * C + (c0 + tx)];
    __syncthreads();
#pragma unroll
    for (int i = 0; i < 32; i += 8)
        g_xT[(size_t)(c0 + ty + i) * BATCH + (b0 + tx)] =
            __float2half_rn(tile[tx][ty + i]);
}

// ---- one LCN layer: yT[j,:] = relu(sum_k srcT[knn[j,k],:] * w[j,k] + b[j])
// 128 threads, each owns 4 batch elements (uint2 = 4 halves = 8 B per load).
__global__ void __launch_bounds__(128)
layer_kernel(const __half* __restrict__ srcT,
             const int* __restrict__ knn,
             const float* __restrict__ w,
             const float* __restrict__ bias,
             __half* __restrict__ dstT)
{
    const int j   = blockIdx.x;
    const int tid = threadIdx.x;            // 0..127

    __shared__ int   sidx[KNN];
    __shared__ float sw[KNN];
    if (tid < KNN) {
        const int stride = g_knn_stride;    // 1 (int32) or 2 (int64 low word)
        sidx[tid] = knn[((size_t)j * KNN + tid) * stride];
        sw[tid]   = w[(size_t)j * KNN + tid];
    }
    __syncthreads();

    const uint2* src2 = (const uint2*)srcT;   // 4 halves per element
    float ax = 0.f, ay = 0.f, az = 0.f, aw = 0.f;

#pragma unroll
    for (int k = 0; k < KNN; ++k) {
        const uint2  raw = __ldg(&src2[(size_t)sidx[k] * 128 + tid]);
        const float2 lo  = __half22float2(*(const __half2*)&raw.x);
        const float2 hi  = __half22float2(*(const __half2*)&raw.y);
        const float  wk  = sw[k];
        ax = fmaf(lo.x, wk, ax);
        ay = fmaf(lo.y, wk, ay);
        az = fmaf(hi.x, wk, az);
        aw = fmaf(hi.y, wk, aw);
    }

    const float bb = bias[j];
    ax = fmaxf(ax + bb, 0.f);
    ay = fmaxf(ay + bb, 0.f);
    az = fmaxf(az + bb, 0.f);
    aw = fmaxf(aw + bb, 0.f);

    uint2 out;
    *(__half2*)&out.x = __floats2half2_rn(ax, ay);
    *(__half2*)&out.y = __floats2half2_rn(az, aw);
    ((uint2*)dstT)[(size_t)j * 128 + tid] = out;
}

// ---- FC: out[b, o] = fc_b[o] + sum_j y2T[j, b] * fc_w[j, o] ---------------
__global__ void fc_init_kernel(float* __restrict__ out, const float* __restrict__ fc_b)
{
    int i = blockIdx.x * blockDim.x + threadIdx.x;
    if (i < BATCH * 16) out[i] = fc_b[i & 15];
}

__global__ void __launch_bounds__(128)
fc_kernel(const float* __restrict__ fc_w, float* __restrict__ out)
{
    // grid.x: 4 batch tiles of 128; grid.y: 16 j tiles of 128 (2048 total)
    const int b  = blockIdx.x * 128 + threadIdx.x;
    const int j0 = blockIdx.y * 128;

    float acc[16];
#pragma unroll
    for (int o = 0; o < 16; ++o) acc[o] = 0.f;

    for (int jj = 0; jj < 128; ++jj) {
        const int   j = j0 + jj;
        const float v = __half2float(g_y2[(size_t)j * BATCH + b]);
#pragma unroll
        for (int o = 0; o < 16; ++o)
            acc[o] = fmaf(v, __ldg(&fc_w[j * 16 + o]), acc[o]);
    }
#pragma unroll
    for (int o = 0; o < 16; ++o)
        atomicAdd(&out[b * 16 + o], acc[o]);
}

// ---------------------------------------------------------------------------
extern "C" void kernel_launch(void* const* d_in, const int* in_sizes, int n_in,
                              void* d_out, int out_size)
{
    const float *x, *w0, *b0, *w1, *b1, *w2, *b2, *fcw, *fcb;
    const int *k0, *k1, *k2;

    // Disambiguate metadata ordering via element counts:
    //   dict order:      x,w0,b0,knn0,w1,b1,knn1,w2,b2,knn2,fc_w,fc_b
    //   signature order: x,w0,b0,w1,b1,w2,b2,fc_w,fc_b,knn0,knn1,knn2
    // in_sizes[3] = 262144 (knn0) in dict order, 131072 (w1) in signature order.
    if (in_sizes[3] == 262144) {
        x   = (const float*)d_in[0];
        w0  = (const float*)d_in[1];  b0 = (const float*)d_in[2];
        k0  = (const int*)d_in[3];
        w1  = (const float*)d_in[4];  b1 = (const float*)d_in[5];
        k1  = (const int*)d_in[6];
        w2  = (const float*)d_in[7];  b2 = (const float*)d_in[8];
        k2  = (const int*)d_in[9];
        fcw = (const float*)d_in[10]; fcb = (const float*)d_in[11];
    } else {
        x   = (const float*)d_in[0];
        w0  = (const float*)d_in[1];  b0 = (const float*)d_in[2];
        w1  = (const float*)d_in[3];  b1 = (const float*)d_in[4];
        w2  = (const float*)d_in[5];  b2 = (const float*)d_in[6];
        fcw = (const float*)d_in[7];  fcb = (const float*)d_in[8];
        k0  = (const int*)d_in[9];
        k1  = (const int*)d_in[10];
        k2  = (const int*)d_in[11];
    }

    __half *p_xT, *p_y0, *p_y1, *p_y2;
    cudaGetSymbolAddress((void**)&p_xT, g_xT);
    cudaGetSymbolAddress((void**)&p_y0, g_y0);
    cudaGetSymbolAddress((void**)&p_y1, g_y1);
    cudaGetSymbolAddress((void**)&p_y2, g_y2);

    float* out = (float*)d_out;

    // 0) probe knn dtype (int32 vs int64) — 1 warp, parallel
    detect_kernel<<<1, 32>>>(k0);

    // 1) transpose x (512, 16384) fp32 -> xT (16384, 512) fp16
    transpose_kernel<<<dim3(16384 / 32, BATCH / 32), dim3(32, 8)>>>(x, 16384);

    // 2) three LCN layers (feature-major fp16 in/out, fp32 math)
    layer_kernel<<<8192, 128>>>(p_xT, k0, w0, b0, p_y0);
    layer_kernel<<<4096, 128>>>(p_y0, k1, w1, b1, p_y1);
    layer_kernel<<<2048, 128>>>(p_y1, k2, w2, b2, p_y2);

    // 3) FC head
    fc_init_kernel<<<(BATCH * 16 + 255) / 256, 256>>>(out, fcb);
    fc_kernel<<<dim3(BATCH / 128, 2048 / 128), 128>>>(fcw, out);
}